// round 2
// baseline (speedup 1.0000x reference)
#include <cuda_runtime.h>
#include <math.h>

#define LD 65  // padded row stride for 64x64 tiles in smem (conflict-free both axes)

// ---------------- intermediates (device globals; no allocation allowed) ---------------
__device__ float g_Mp0[64 * 64];     // (n1, n2) : feat_tra @ feat_det^T + iou
__device__ float g_m1[64 * 512];
__device__ float g_m2[64 * 512];
__device__ float g_u1[64 * 512];
__device__ float g_u2[64 * 512];
__device__ float g_e1[64 * 512];
__device__ float g_e2[64 * 512];
__device__ float g_P[64 * 64];       // P[a,b] = Mp[b,a] = e1[b] . e2[a]   (a over n2, b over n1)

__device__ __forceinline__ float warpSum(float v) {
#pragma unroll
    for (int o = 16; o; o >>= 1) v += __shfl_xor_sync(0xffffffffu, v, o);
    return v;
}
__device__ __forceinline__ float warpMax(float v) {
#pragma unroll
    for (int o = 16; o; o >>= 1) v = fmaxf(v, __shfl_xor_sync(0xffffffffu, v, o));
    return v;
}

// ---------------- Mp0 = feat_tra @ feat_det^T + iou : warp per output --------------
__global__ void k_mp0(const float* __restrict__ tra, const float* __restrict__ det,
                      const float* __restrict__ iou) {
    int g = blockIdx.x * 32 + (threadIdx.x >> 5);
    int lane = threadIdx.x & 31;
    int i = g >> 6, j = g & 63;
    const float* a = tra + i * 512;
    const float* b = det + j * 512;
    float s = 0.f;
#pragma unroll 4
    for (int k = lane; k < 512; k += 32) s += a[k] * b[k];
    s = warpSum(s);
    if (!lane) g_Mp0[i * 64 + j] = s + iou[i * 64 + j];
}

// ---------------- m1 = Mp0 @ det, m2 = Mp0^T @ tra : thread per output -------------
__global__ void k_m12(const float* __restrict__ tra, const float* __restrict__ det) {
    int t = blockIdx.x * blockDim.x + threadIdx.x;
    if (t < 32768) {
        int i = t >> 9, k = t & 511;
        float s = 0.f;
#pragma unroll 8
        for (int j = 0; j < 64; j++) s += g_Mp0[i * 64 + j] * det[j * 512 + k];
        g_m1[t] = s;
    } else {
        int t2 = t - 32768;
        int j = t2 >> 9, k = t2 & 511;
        float s = 0.f;
#pragma unroll 8
        for (int i = 0; i < 64; i++) s += g_Mp0[i * 64 + j] * tra[i * 512 + k];
        g_m2[t2] = s;
    }
}

// ---------------- u = feat + lam * m, lam = |feat| / |m| ---------------------------
__global__ void k_u(const float* __restrict__ tra, const float* __restrict__ det) {
    __shared__ float pf[16], pm[16];
    __shared__ float sLam;
    int r = blockIdx.x;
    const float* f;
    const float* m;
    float* u;
    if (r < 64) { f = tra + r * 512; m = g_m1 + r * 512; u = g_u1 + r * 512; }
    else        { r -= 64; f = det + r * 512; m = g_m2 + r * 512; u = g_u2 + r * 512; }
    int t = threadIdx.x;
    float fv = f[t], mv = m[t];
    float sf = warpSum(fv * fv);
    float sm = warpSum(mv * mv);
    int w = t >> 5, lane = t & 31;
    if (!lane) { pf[w] = sf; pm[w] = sm; }
    __syncthreads();
    if (t < 32) {
        float a = (t < 16) ? pf[t] : 0.f;
        float b = (t < 16) ? pm[t] : 0.f;
        a = warpSum(a);
        b = warpSum(b);
        if (!t) sLam = sqrtf(a) / sqrtf(b);
    }
    __syncthreads();
    u[t] = fv + sLam * mv;
}

// ---------------- e = relu(u @ W^T + b) : warp per output --------------------------
__global__ void k_egemm(const float* __restrict__ W, const float* __restrict__ bias) {
    int gw = blockIdx.x * 32 + (threadIdx.x >> 5);
    int lane = threadIdx.x & 31;
    int tensor = gw >> 15;
    int loc = gw & 32767;
    int i = loc >> 9, j = loc & 511;
    const float* u = (tensor ? g_u2 : g_u1) + i * 512;
    const float* w = W + j * 512;
    float s = 0.f;
#pragma unroll 4
    for (int k = lane; k < 512; k += 32) s += u[k] * w[k];
    s = warpSum(s);
    if (!lane) {
        float v = fmaxf(s + bias[j], 0.f);
        (tensor ? g_e2 : g_e1)[i * 512 + j] = v;
    }
}

// ---------------- row-wise L2 normalize e in place ---------------------------------
__global__ void k_enorm() {
    __shared__ float p[16];
    __shared__ float sScale;
    int r = blockIdx.x;
    float* e = (r < 64) ? (g_e1 + r * 512) : (g_e2 + (r - 64) * 512);
    int t = threadIdx.x;
    float v = e[t];
    float s = warpSum(v * v);
    if (!(t & 31)) p[t >> 5] = s;
    __syncthreads();
    if (t < 32) {
        float a = (t < 16) ? p[t] : 0.f;
        a = warpSum(a);
        if (!t) sScale = 1.f / fmaxf(sqrtf(a), 1e-12f);
    }
    __syncthreads();
    e[t] = v * sScale;
}

// ---------------- P[a,b] = e1[b] . e2[a] : warp per output --------------------------
__global__ void k_P() {
    int g = blockIdx.x * 32 + (threadIdx.x >> 5);
    int lane = threadIdx.x & 31;
    int a = g >> 6, b = g & 63;
    const float* x = g_e1 + b * 512;
    const float* y = g_e2 + a * 512;
    float s = 0.f;
#pragma unroll 4
    for (int k = lane; k < 512; k += 32) s += x[k] * y[k];
    s = warpSum(s);
    if (!lane) g_P[a * 64 + b] = s;
}

// ---------------- ADMM + PCG, everything in shared memory, one block ---------------
// K = beta*I + rho*(I(x)J + J(x)I) - 0.5*(D_p*S + S*D_p),  S = (J-I)(x)(J-I)
// Matvec:  (Kd)[a,b] = beta*d + rho*(Rd_a + Cd_b)
//                      - 0.5*( P*(Td - Rd_a - Cd_b + d) + (Te - Re_a - Ce_b + e) ),  e = P.*d
// Preconditioner B = beta*I + rho*(I(x)J + J(x)I):
//   (B^-1 r)[a,b] = r/beta + cRC*(Rr_a + Cr_b) + cT*Tr
__global__ void __launch_bounds__(1024, 1) k_admm(float* __restrict__ out) {
    extern __shared__ float sm[];
    float* X  = sm;            // 4160 each (64*65)
    float* Rr = sm + 4160;
    float* Dd = sm + 8320;
    float* Qv = sm + 12480;
    float* Z1 = sm + 16640;
    float* Y1 = sm + 20800;
    float* Pm = sm + 24960;
    float* RA  = sm + 29120;   // 64 each
    float* CA  = RA + 64;
    float* RB  = CA + 64;
    float* CB  = RB + 64;
    float* y2c = CB + 64;
    float* y2r = y2c + 64;
    float* part = y2r + 64;    // 32
    float* scal = part + 32;   // 8

    const float rho   = 100.f;
    const float sigma = 1e-3f;
    const float beta  = 3969.f + rho + sigma;        // (n1-1)(n2-1) + rho + sigma
    const float binv  = 1.f / beta;
    const float b64i  = 1.f / (beta + 64.f * rho);
    const float b128i = 1.f / (beta + 128.f * rho);
    const float cRC   = (b64i - binv) * (1.f / 64.f);
    const float cT    = (b128i - 2.f * b64i + binv) * (1.f / 4096.f);

    int tid = threadIdx.x;
    int w = tid >> 5, lane = tid & 31;
    int a0 = tid >> 6, b0 = tid & 63;
    int off[4], aa[4];
#pragma unroll
    for (int k = 0; k < 4; k++) { aa[k] = a0 + 16 * k; off[k] = aa[k] * LD + b0; }

    // init state
#pragma unroll
    for (int k = 0; k < 4; k++) {
        X[off[k]] = 0.f; Z1[off[k]] = 0.f; Y1[off[k]] = 0.f;
        Pm[off[k]] = g_P[aa[k] * 64 + b0];
    }
    if (tid < 64) { y2c[tid] = 0.f; y2r[tid] = 0.f; }
    __syncthreads();

    auto blockRed = [&](float v, int slot) {
        v = warpSum(v);
        if (!lane) part[w] = v;
        __syncthreads();
        if (w == 0) {
            float x = part[lane];
            x = warpSum(x);
            if (!lane) scal[slot] = x;
        }
        __syncthreads();
    };

    // row/col/total sums of M  -> RA, CA, scal[0]
    auto sums1 = [&](const float* M) {
#pragma unroll
        for (int rr = 0; rr < 2; rr++) {
            int r = 2 * w + rr;
            float v = M[r * LD + lane] + M[r * LD + lane + 32];
            v = warpSum(v);
            if (!lane) RA[r] = v;
            float u = M[lane * LD + r] + M[(lane + 32) * LD + r];
            u = warpSum(u);
            if (!lane) CA[r] = u;
        }
        __syncthreads();
        if (w == 0) {
            float v = warpSum(RA[lane] + RA[lane + 32]);
            if (!lane) scal[0] = v;
        }
        __syncthreads();
    };

    // sums of M (RA,CA,scal[0]) and of P.*M (RB,CB,scal[1])
    auto sums2 = [&](const float* M) {
#pragma unroll
        for (int rr = 0; rr < 2; rr++) {
            int r = 2 * w + rr;
            float m0 = M[r * LD + lane], m1v = M[r * LD + lane + 32];
            float p0 = Pm[r * LD + lane], p1 = Pm[r * LD + lane + 32];
            float va = warpSum(m0 + m1v);
            float vb = warpSum(p0 * m0 + p1 * m1v);
            if (!lane) { RA[r] = va; RB[r] = vb; }
            float c0 = M[lane * LD + r], c1 = M[(lane + 32) * LD + r];
            float q0 = Pm[lane * LD + r], q1 = Pm[(lane + 32) * LD + r];
            float ua = warpSum(c0 + c1);
            float ub = warpSum(q0 * c0 + q1 * c1);
            if (!lane) { CA[r] = ua; CB[r] = ub; }
        }
        __syncthreads();
        if (w == 0) {
            float v = warpSum(RA[lane] + RA[lane + 32]);
            if (!lane) scal[0] = v;
        } else if (w == 1) {
            float v = warpSum(RB[lane] + RB[lane + 32]);
            if (!lane) scal[1] = v;
        }
        __syncthreads();
    };

    auto applyK = [&](float d, float p, int a, int b, float TA, float TB) -> float {
        float e = p * d;
        return beta * d + rho * (RA[a] + CA[b])
             - 0.5f * (p * (TA - RA[a] - CA[b] + d) + (TB - RB[a] - CB[b] + e));
    };

    for (int it = 0; it < 150; ++it) {
        // r = rhs - K x   (warm start from previous x), also |rhs|^2
        sums2(X);
        {
            float TA = scal[0], TB = scal[1];
            float loc = 0.f;
#pragma unroll
            for (int k = 0; k < 4; k++) {
                int o = off[k], a = aa[k];
                float x = X[o], p = Pm[o];
                float kx = applyK(x, p, a, b0, TA, TB);
                float rhs = sigma * x + p + (rho * Z1[o] - Y1[o])
                          + (rho - y2c[b0]) + (rho - y2r[a]);
                Rr[o] = rhs - kx;
                loc += rhs * rhs;
            }
            blockRed(loc, 2);
        }
        float tol2 = fmaxf(scal[2] * 1e-14f, 1e-30f);

        // z0 = B^-1 r; d0 = z0; rho_s = r.z
        sums1(Rr);
        {
            float TR = scal[0];
            float loc = 0.f;
#pragma unroll
            for (int k = 0; k < 4; k++) {
                int o = off[k];
                float r = Rr[o];
                float z = binv * r + cRC * (RA[aa[k]] + CA[b0]) + cT * TR;
                Dd[o] = z;
                loc += r * z;
            }
            blockRed(loc, 3);
        }
        float rho_s = scal[3];

        if (rho_s > 0.f) {
            float prev_rn2 = 3.4e38f;
            int stagn = 0;
            for (int cg = 0; cg < 150; ++cg) {
                sums2(Dd);
                float TA = scal[0], TB = scal[1];
                float loc = 0.f;
#pragma unroll
                for (int k = 0; k < 4; k++) {
                    int o = off[k];
                    float d = Dd[o], p = Pm[o];
                    float q = applyK(d, p, aa[k], b0, TA, TB);
                    Qv[o] = q;
                    loc += d * q;
                }
                blockRed(loc, 2);
                float dq = scal[2];
                if (!(dq > 0.f)) break;
                float alpha = rho_s / dq;
                loc = 0.f;
#pragma unroll
                for (int k = 0; k < 4; k++) {
                    int o = off[k];
                    X[o] += alpha * Dd[o];
                    float r = Rr[o] - alpha * Qv[o];
                    Rr[o] = r;
                    loc += r * r;
                }
                blockRed(loc, 2);
                float rn2 = scal[2];
                if (rn2 <= tol2) break;
                if (rn2 >= 0.99f * prev_rn2) { if (++stagn >= 3) break; }
                else stagn = 0;
                prev_rn2 = rn2;

                sums1(Rr);
                float TR = scal[0];
                loc = 0.f;
#pragma unroll
                for (int k = 0; k < 4; k++) {
                    int o = off[k];
                    float r = Rr[o];
                    float z = binv * r + cRC * (RA[aa[k]] + CA[b0]) + cT * TR;
                    loc += r * z;
                }
                blockRed(loc, 3);
                float rho_n = scal[3];
                float bk = rho_n / rho_s;
                rho_s = rho_n;
#pragma unroll
                for (int k = 0; k < 4; k++) {
                    int o = off[k];
                    float r = Rr[o];
                    float z = binv * r + cRC * (RA[aa[k]] + CA[b0]) + cT * TR;
                    Dd[o] = z + bk * Dd[o];
                }
                __syncthreads();
            }
        }

        // z, y updates
        sums1(X);
#pragma unroll
        for (int k = 0; k < 4; k++) {
            int o = off[k];
            float x = X[o];
            float v = x + Y1[o] * (1.f / rho);
            float zn = fminf(fmaxf(v, 0.f), 1e6f);
            Y1[o] += rho * (x - zn);
            Z1[o] = zn;
        }
        if (tid < 64) {
            y2c[tid] += rho * (CA[tid] - 1.f);
            y2r[tid] += rho * (RA[tid] - 1.f);
        }
        __syncthreads();
    }

    // out[0][j][i] = softmax_i( 200 * clip(X[i][j], 0, 1) )  -> column-wise softmax of X
#pragma unroll
    for (int rr = 0; rr < 2; rr++) {
        int c = 2 * w + rr;
        float v1 = fminf(fmaxf(X[lane * LD + c], 0.f), 1.f);
        float v2 = fminf(fmaxf(X[(lane + 32) * LD + c], 0.f), 1.f);
        float mx = warpMax(fmaxf(v1, v2));
        float e1v = expf(200.f * (v1 - mx));
        float e2v = expf(200.f * (v2 - mx));
        float s = warpSum(e1v + e2v);
        out[c * 64 + lane] = e1v / s;
        out[c * 64 + lane + 32] = e2v / s;
    }
}

// ------------------------------------------------------------------------------------
extern "C" void kernel_launch(void* const* d_in, const int* in_sizes, int n_in,
                              void* d_out, int out_size) {
    const float* tra = (const float*)d_in[0];   // (64,512)
    const float* det = (const float*)d_in[1];   // (64,512)
    const float* iou = (const float*)d_in[2];   // (64,64)
    const float* W   = (const float*)d_in[3];   // (512,512)
    const float* b   = (const float*)d_in[4];   // (512,)
    float* out = (float*)d_out;                 // (1,64,64)

    const int SMEM_BYTES = (29120 + 6 * 64 + 32 + 8) * 4;  // 118176
    cudaFuncSetAttribute(k_admm, cudaFuncAttributeMaxDynamicSharedMemorySize, SMEM_BYTES);

    k_mp0<<<128, 1024>>>(tra, det, iou);
    k_m12<<<64, 1024>>>(tra, det);
    k_u<<<128, 512>>>(tra, det);
    k_egemm<<<2048, 1024>>>(W, b);
    k_enorm<<<128, 512>>>();
    k_P<<<128, 1024>>>();
    k_admm<<<1, 1024, SMEM_BYTES>>>(out);
}